// round 16
// baseline (speedup 1.0000x reference)
#include <cuda_runtime.h>
#include <math_constants.h>
#include <cstdint>

#define SEQ    2048
#define DMODEL 1024
#define NH     16
#define DH     64
#define BATCH  2
#define MTOT   (BATCH*SEQ)   // 4096 rows

// ---------------------------------------------------------------------------
// Device scratch (allocation-free rule)
// ---------------------------------------------------------------------------
__device__ float g_Q[(size_t)MTOT*DMODEL];
__device__ float g_Kc[(size_t)MTOT*DMODEL];        // compacted projected K
__device__ float g_Vtc[(size_t)BATCH*NH*DH*SEQ];   // compacted projected V, transposed
__device__ float g_O[(size_t)MTOT*DMODEL];
__device__ float g_Wt[4][(size_t)DMODEL*DMODEL];   // transposed+rounded weights [N][K]
__device__ float g_R[3][(size_t)MTOT*DMODEL];      // rounded q; compacted+rounded k,v inputs
__device__ int   g_idx[BATCH*SEQ];                 // kept-token old indices
__device__ int   g_nkeep[BATCH];

// ---------------------------------------------------------------------------
// Helpers
// ---------------------------------------------------------------------------
__device__ __forceinline__ uint32_t smem_u32(const void* p) {
    uint32_t a;
    asm("{ .reg .u64 t; cvta.to.shared.u64 t, %1; cvt.u32.u64 %0, t; }" : "=r"(a) : "l"(p));
    return a;
}
__device__ __forceinline__ float to_tf32_rn(float x) {
    uint32_t r;
    asm("cvt.rna.tf32.f32 %0, %1;" : "=r"(r) : "f"(x));
    return __uint_as_float(r);
}
__device__ __forceinline__ float ex2f(float y) {    // 2^y via MUFU
    float r;
    asm("ex2.approx.f32 %0, %1;" : "=f"(r) : "f"(y));
    return r;
}
__device__ __forceinline__ void cp16(uint32_t dst, const void* src) {
    asm volatile("cp.async.cg.shared.global [%0], [%1], 16;" :: "r"(dst), "l"(src));
}
#define CP_COMMIT() asm volatile("cp.async.commit_group;" ::: "memory")
#define CP_WAIT0()  asm volatile("cp.async.wait_group 0;" ::: "memory")
#define CP_WAIT1()  asm volatile("cp.async.wait_group 1;" ::: "memory")

// ldmatrix x4: four 8x8 b16 tiles == four 8x4 f32 tiles (tf32 fragment layout)
__device__ __forceinline__ void ldsm4(uint32_t& r0, uint32_t& r1, uint32_t& r2,
                                      uint32_t& r3, uint32_t addr) {
    asm volatile("ldmatrix.sync.aligned.m8n8.x4.shared.b16 {%0,%1,%2,%3}, [%4];"
                 : "=r"(r0), "=r"(r1), "=r"(r2), "=r"(r3) : "r"(addr));
}

// m16n8k8 tf32 mma (baseline PTX, sm_80+)
__device__ __forceinline__ void mma_tf32(float* c, const uint32_t* a, const uint32_t* b) {
    asm volatile(
        "mma.sync.aligned.m16n8k8.row.col.f32.tf32.tf32.f32 "
        "{%0,%1,%2,%3}, {%4,%5,%6,%7}, {%8,%9}, {%0,%1,%2,%3};"
        : "+f"(c[0]), "+f"(c[1]), "+f"(c[2]), "+f"(c[3])
        : "r"(a[0]), "r"(a[1]), "r"(a[2]), "r"(a[3]), "r"(b[0]), "r"(b[1]));
}

// ---------------------------------------------------------------------------
// Mask compaction: per batch, list of kept token indices + count
// ---------------------------------------------------------------------------
__global__ void compact_idx_kernel(const int* __restrict__ masks) {
    const int b = blockIdx.x;
    const int lane = threadIdx.x;   // 32 threads
    int off = 0;
    for (int c = 0; c < SEQ; c += 32) {
        int m = masks[b * SEQ + c + lane];
        unsigned bal = __ballot_sync(0xffffffffu, m != 0);
        int pre = __popc(bal & ((1u << lane) - 1));
        if (m) g_idx[b * SEQ + off + pre] = c + lane;
        off += __popc(bal);
    }
    if (lane == 0) g_nkeep[b] = off;
}

// ---------------------------------------------------------------------------
// Fused prep: one launch does all independent pre-passes.
//   z=0: round queries -> g_R[0]                     (blocks x < 512)
//   z=1: transpose+round 4 weight matrices -> g_Wt   (blocks x < 4096)
//   z=2: compact+round key inputs   -> g_R[1]        (blocks x < MTOT)
//   z=3: compact+round value inputs -> g_R[2]        (blocks x < MTOT)
// ---------------------------------------------------------------------------
struct PrepArgs {
    const float4* q;
    const float*  ws[4];
    const float*  kv[2];
};

__global__ __launch_bounds__(256) void prep_kernel(PrepArgs p) {
    __shared__ float tile[32][33];
    const int z = blockIdx.z;
    const int t = threadIdx.x;

    if (z == 0) {
        if (blockIdx.x >= 512) return;
        float4* D = (float4*)(g_R[0]);
        const int n4 = MTOT * DMODEL / 4;
        for (int i = blockIdx.x * 256 + t; i < n4; i += 512 * 256) {
            float4 v = p.q[i];
            v.x = to_tf32_rn(v.x); v.y = to_tf32_rn(v.y);
            v.z = to_tf32_rn(v.z); v.w = to_tf32_rn(v.w);
            D[i] = v;
        }
    } else if (z == 1) {
        const int bi = blockIdx.x;           // 0..4095 = (32 x, 32 y, 4 w)
        const int w  = bi >> 10;
        const int x0 = (bi & 31) * 32;
        const int y0 = ((bi >> 5) & 31) * 32;
        const int tx = t & 31, ty = t >> 5;  // (32, 8)
        const float* S = p.ws[w];
        float*       D = g_Wt[w];
        #pragma unroll
        for (int j = 0; j < 32; j += 8)
            tile[ty + j][tx] = S[(size_t)(y0 + ty + j) * DMODEL + x0 + tx];
        __syncthreads();
        #pragma unroll
        for (int j = 0; j < 32; j += 8)
            D[(size_t)(x0 + ty + j) * DMODEL + y0 + tx] = to_tf32_rn(tile[tx][ty + j]);
    } else {
        const int zz  = z - 2;               // 0=keys, 1=values
        const int row = blockIdx.x;          // 0..MTOT-1
        const int b = row >> 11;
        const int j = row & (SEQ - 1);
        const int nk = g_nkeep[b];
        const int pad = (nk + 127) & ~127;
        if (j >= pad) return;
        float4* dst = (float4*)(g_R[1 + zz] + (size_t)row * DMODEL);
        if (j < nk) {
            const float4* src = (const float4*)(p.kv[zz] +
                ((size_t)(b * SEQ + g_idx[b * SEQ + j])) * DMODEL);
            float4 v = src[t];
            v.x = to_tf32_rn(v.x); v.y = to_tf32_rn(v.y);
            v.z = to_tf32_rn(v.z); v.w = to_tf32_rn(v.w);
            dst[t] = v;
        } else {
            dst[t] = make_float4(0.f, 0.f, 0.f, 0.f);
        }
    }
}

// ---------------------------------------------------------------------------
// tf32 tensor-core GEMM (cp.async 3-stage, ldmatrix fragments).
// Batched over blockIdx.z. z==2 (V projection) stores transposed to g_Vtc.
// COMPACT: z>=1 CTAs early-exit beyond the batch's padded keep count.
// ---------------------------------------------------------------------------
#define BM 128
#define BN 128
#define BK 32
#define KT_GEMM (DMODEL / BK)          // 32
#define ROWP 36
#define ROWB (ROWP * 4)                // 144 bytes per row
#define TILE_F (128 * ROWP)
#define GSTG 3
#define SM_GEMM_BYTES (GSTG * 2 * TILE_F * 4)   // 110592 B

struct GemmBatch { const float* A[3]; const float* B[3]; float* C[3]; };

template<bool COMPACT>
__global__ __launch_bounds__(256, 2) void gemm_tf32_kernel(GemmBatch gb) {
    extern __shared__ float sm[];
    const uint32_t sb = smem_u32(sm);

    const int m0 = blockIdx.y * BM;
    if (COMPACT && blockIdx.z != 0) {
        const int b = m0 >> 11;
        const int pad = (g_nkeep[b] + 127) & ~127;
        if ((m0 & (SEQ - 1)) >= pad) return;   // tile entirely beyond kept rows
    }

    const float* __restrict__ A  = gb.A[blockIdx.z];
    const float* __restrict__ Bt = gb.B[blockIdx.z];
    float* __restrict__ C        = gb.C[blockIdx.z];

    const int t     = threadIdx.x;
    const int wid   = t >> 5;
    const int lane  = t & 31;
    const int wm    = wid & 1;
    const int wn    = wid >> 1;
    const int lane4 = lane >> 2;
    const int lanek = lane & 3;
    const int lm    = lane >> 3;
    const int lr    = lane & 7;
    const int n0 = blockIdx.x * BN;
    const int lrow = t >> 3, lc4 = t & 7;

    const uint32_t aOff = (uint32_t)((wm * 64 + (lm & 1) * 8 + lr) * ROWB + (lm >> 1) * 16);
    const uint32_t bOff = (uint32_t)((wn * 32 + (lm >> 1) * 8 + lr) * ROWB + (lm & 1) * 16);

    float acc[4][4][4];
    #pragma unroll
    for (int mi = 0; mi < 4; mi++)
        #pragma unroll
        for (int ni = 0; ni < 4; ni++)
            #pragma unroll
            for (int f = 0; f < 4; f++) acc[mi][ni][f] = 0.f;

    auto issue = [&](int kt, int s) {
        const float* Ap = A  + (size_t)m0 * DMODEL + kt * BK;
        const float* Bp = Bt + (size_t)n0 * DMODEL + kt * BK;
        #pragma unroll
        for (int i = 0; i < 4; i++) {
            int row = lrow + i * 32;
            cp16(sb + (uint32_t)((s * 2 * TILE_F + row * ROWP + lc4 * 4) * 4),
                 Ap + (size_t)row * DMODEL + lc4 * 4);
            cp16(sb + (uint32_t)((s * 2 * TILE_F + TILE_F + row * ROWP + lc4 * 4) * 4),
                 Bp + (size_t)row * DMODEL + lc4 * 4);
        }
        CP_COMMIT();
    };

    issue(0, 0);
    issue(1, 1);

    for (int kt = 0; kt < KT_GEMM; kt++) {
        const int s = kt % 3;
        if (kt < KT_GEMM - 1) CP_WAIT1(); else CP_WAIT0();
        __syncthreads();
        if (kt + 2 < KT_GEMM) issue(kt + 2, (kt + 2) % 3);

        const uint32_t aAdr = sb + (uint32_t)(s * 2 * TILE_F * 4) + aOff;
        const uint32_t bAdr = aAdr - aOff + (uint32_t)(TILE_F * 4) + bOff;
        #pragma unroll
        for (int ks = 0; ks < 4; ks++) {
            uint32_t a[4][4], b[4][2];
            #pragma unroll
            for (int mi = 0; mi < 4; mi++)
                ldsm4(a[mi][0], a[mi][1], a[mi][2], a[mi][3],
                      aAdr + (uint32_t)(mi * 16 * ROWB + ks * 32));
            ldsm4(b[0][0], b[0][1], b[1][0], b[1][1], bAdr + (uint32_t)(ks * 32));
            ldsm4(b[2][0], b[2][1], b[3][0], b[3][1],
                  bAdr + (uint32_t)(16 * ROWB + ks * 32));
            #pragma unroll
            for (int mi = 0; mi < 4; mi++)
                #pragma unroll
                for (int ni = 0; ni < 4; ni++)
                    mma_tf32(acc[mi][ni], a[mi], b[ni]);
        }
    }

    const bool vt = COMPACT && (blockIdx.z == 2);
    #pragma unroll
    for (int mi = 0; mi < 4; mi++) {
        #pragma unroll
        for (int ni = 0; ni < 4; ni++) {
            int row = m0 + wm * 64 + mi * 16 + lane4;
            int col = n0 + wn * 32 + ni * 8 + 2 * lanek;
            float v0 = acc[mi][ni][0], v1 = acc[mi][ni][1];
            float v2 = acc[mi][ni][2], v3 = acc[mi][ni][3];
            if (COMPACT) {
                v0 = to_tf32_rn(v0); v1 = to_tf32_rn(v1);
                v2 = to_tf32_rn(v2); v3 = to_tf32_rn(v3);
            }
            if (vt) {
                int bb = row >> 11, tok = row & (SEQ - 1);   // compacted token idx
                int hh = col >> 6,  dh  = col & (DH - 1);
                float* base = g_Vtc + ((size_t)(bb * NH + hh) * DH + dh) * SEQ + tok;
                base[0]       = v0;
                base[SEQ]     = v1;
                base[8]       = v2;
                base[SEQ + 8] = v3;
            } else {
                *(float2*)(C + (size_t)row * DMODEL + col)       = make_float2(v0, v1);
                *(float2*)(C + (size_t)(row + 8) * DMODEL + col) = make_float2(v2, v3);
            }
        }
    }
}

// ---------------------------------------------------------------------------
// Tensor-core flash attention over COMPACTED KV (unchanged from R12).
// ---------------------------------------------------------------------------
#define ATT_BQ   128
#define ATT_BKV  64
#define APAD     68
#define ATT_KV_F (2 * ATT_BKV * APAD)
#define ATT_P_OFF (2 * ATT_KV_F)
#define ATT_MSK_OFF (ATT_P_OFF + ATT_BQ * APAD)
#define ATT_SMEM ((ATT_MSK_OFF + SEQ) * 4)            // 112640 B

__global__ __launch_bounds__(128, 2) void attn_mma_kernel() {
    extern __shared__ float smf[];
    const uint32_t sb = smem_u32(smf);
    float* msf = smf + ATT_MSK_OFF;

    const int t    = threadIdx.x;
    const int w    = t >> 5;
    const int lane = t & 31;
    const int gid  = lane >> 2;
    const int tid4 = lane & 3;
    const int lm   = lane >> 3;
    const int lr   = lane & 7;
    const int b  = blockIdx.z;
    const int h  = blockIdx.y;
    const int q0 = blockIdx.x * ATT_BQ;

    const int nk  = g_nkeep[b];
    const int pad = (nk + 63) & ~63;

    for (int i = t; i < pad; i += 128)
        msf[i] = (i < nk) ? 0.f : -1e30f;

    const uint32_t kCol = (uint32_t)(((lm >> 1) * 8 + (lm & 1) * 4) * 4);
    const uint32_t vRow = (uint32_t)(((lm >> 1) * 8 + lr) * APAD * 4);
    const uint32_t vCol = (uint32_t)((lm & 1) * 16);
    uint32_t pAdrM[2];
    #pragma unroll
    for (int mi = 0; mi < 2; mi++)
        pAdrM[mi] = sb + (uint32_t)((ATT_P_OFF + (w * 32 + mi * 16 + (lm & 1) * 8 + lr) * APAD) * 4)
                  + (uint32_t)((lm >> 1) * 16);

    const float qs = 0.125f * 1.4426950408889634f;
    uint32_t aQ[2][8][4];
    {
        const float* Qb = g_Q + ((size_t)(b * SEQ + q0 + w * 32)) * DMODEL + h * DH;
        #pragma unroll
        for (int mi = 0; mi < 2; mi++) {
            const float* Qm = Qb + (size_t)(mi * 16) * DMODEL;
            #pragma unroll
            for (int kk = 0; kk < 8; kk++) {
                int c = kk * 8 + tid4;
                aQ[mi][kk][0] = __float_as_uint(to_tf32_rn(qs * Qm[(size_t)gid       * DMODEL + c    ]));
                aQ[mi][kk][1] = __float_as_uint(to_tf32_rn(qs * Qm[(size_t)(gid + 8) * DMODEL + c    ]));
                aQ[mi][kk][2] = __float_as_uint(to_tf32_rn(qs * Qm[(size_t)gid       * DMODEL + c + 4]));
                aQ[mi][kk][3] = __float_as_uint(to_tf32_rn(qs * Qm[(size_t)(gid + 8) * DMODEL + c + 4]));
            }
        }
    }

    float Oa[2][8][4];
    #pragma unroll
    for (int mi = 0; mi < 2; mi++)
        #pragma unroll
        for (int nb = 0; nb < 8; nb++)
            #pragma unroll
            for (int f = 0; f < 4; f++) Oa[mi][nb][f] = 0.f;
    float mx[2][2] = {{-1e30f, -1e30f}, {-1e30f, -1e30f}};
    float ls[2][2] = {{0.f, 0.f}, {0.f, 0.f}};

    float* Pw = smf + ATT_P_OFF + w * 32 * APAD;

    auto issue_kv = [&](int kv0, int s) {
        const float* Kb  = g_Kc  + ((size_t)(b * SEQ + kv0)) * DMODEL + h * DH;
        const float* Vtb = g_Vtc + ((size_t)(b * NH + h) * DH) * SEQ + kv0;
        #pragma unroll
        for (int i = 0; i < 8; i++) {
            int idx = i * 128 + t;
            int row = idx >> 4, c4 = (idx & 15) * 4;
            cp16(sb + (uint32_t)((s * ATT_KV_F + row * APAD + c4) * 4),
                 Kb + (size_t)row * DMODEL + c4);
            cp16(sb + (uint32_t)((s * ATT_KV_F + ATT_BKV * APAD + row * APAD + c4) * 4),
                 Vtb + (size_t)row * SEQ + c4);
        }
        CP_COMMIT();
    };

    if (pad > 0) issue_kv(0, 0);

    for (int kv0 = 0; kv0 < pad; kv0 += ATT_BKV) {
        const int s = (kv0 >> 6) & 1;
        CP_WAIT0();
        __syncthreads();
        if (kv0 + ATT_BKV < pad) issue_kv(kv0 + ATT_BKV, s ^ 1);

        const uint32_t ksAdr = sb + (uint32_t)(s * ATT_KV_F * 4);
        const uint32_t vsAdr = ksAdr + (uint32_t)(ATT_BKV * APAD * 4);

        // S phase
        float sc[2][8][4];
        #pragma unroll
        for (int nb = 0; nb < 8; nb++) {
            uint32_t bk[16];
            const uint32_t rowAdr = ksAdr + (uint32_t)(((nb * 8 + lr) * APAD) * 4) + kCol;
            #pragma unroll
            for (int i = 0; i < 4; i++)
                ldsm4(bk[4*i], bk[4*i+1], bk[4*i+2], bk[4*i+3], rowAdr + i * 64);
            #pragma unroll
            for (int f = 0; f < 4; f++) { sc[0][nb][f] = 0.f; sc[1][nb][f] = 0.f; }
            #pragma unroll
            for (int kk = 0; kk < 8; kk++) {
                const uint32_t* bp = &bk[4 * (kk >> 1) + 2 * (kk & 1)];
                mma_tf32(sc[0][nb], aQ[0][kk], bp);
                mma_tf32(sc[1][nb], aQ[1][kk], bp);
            }
        }

        // Tail tile only: -1e30 bias for padded columns
        if (kv0 + ATT_BKV > nk) {
            #pragma unroll
            for (int mi = 0; mi < 2; mi++)
                #pragma unroll
                for (int nb = 0; nb < 8; nb++) {
                    float2 mm = *(const float2*)(msf + kv0 + nb * 8 + 2 * tid4);
                    sc[mi][nb][0] += mm.x; sc[mi][nb][1] += mm.y;
                    sc[mi][nb][2] += mm.x; sc[mi][nb][3] += mm.y;
                }
        }

        // Softmax per m-block
        #pragma unroll
        for (int mi = 0; mi < 2; mi++) {
            float tm0 = -1e30f, tm1 = -1e30f;
            #pragma unroll
            for (int nb = 0; nb < 8; nb++) {
                tm0 = fmaxf(tm0, fmaxf(sc[mi][nb][0], sc[mi][nb][1]));
                tm1 = fmaxf(tm1, fmaxf(sc[mi][nb][2], sc[mi][nb][3]));
            }
            tm0 = fmaxf(tm0, __shfl_xor_sync(0xffffffffu, tm0, 1));
            tm0 = fmaxf(tm0, __shfl_xor_sync(0xffffffffu, tm0, 2));
            tm1 = fmaxf(tm1, __shfl_xor_sync(0xffffffffu, tm1, 1));
            tm1 = fmaxf(tm1, __shfl_xor_sync(0xffffffffu, tm1, 2));

            float mn0 = fmaxf(mx[mi][0], tm0), mn1 = fmaxf(mx[mi][1], tm1);
            float al0 = ex2f(mx[mi][0] - mn0), al1 = ex2f(mx[mi][1] - mn1);
            mx[mi][0] = mn0; mx[mi][1] = mn1;

            float lp0 = 0.f, lp1 = 0.f;
            #pragma unroll
            for (int nb = 0; nb < 8; nb++) {
                float p0 = ex2f(sc[mi][nb][0] - mn0);
                float p1 = ex2f(sc[mi][nb][1] - mn0);
                float p2 = ex2f(sc[mi][nb][2] - mn1);
                float p3 = ex2f(sc[mi][nb][3] - mn1);
                lp0 += p0 + p1; lp1 += p2 + p3;
                *(float2*)(Pw + (mi * 16 + gid) * APAD + nb * 8 + 2 * tid4) =
                    make_float2(to_tf32_rn(p0), to_tf32_rn(p1));
                *(float2*)(Pw + (mi * 16 + gid + 8) * APAD + nb * 8 + 2 * tid4) =
                    make_float2(to_tf32_rn(p2), to_tf32_rn(p3));
            }
            ls[mi][0] = ls[mi][0] * al0 + lp0;
            ls[mi][1] = ls[mi][1] * al1 + lp1;
            #pragma unroll
            for (int nb = 0; nb < 8; nb++) {
                Oa[mi][nb][0] *= al0; Oa[mi][nb][1] *= al0;
                Oa[mi][nb][2] *= al1; Oa[mi][nb][3] *= al1;
            }
        }
        __syncwarp();

        // PV phase
        #pragma unroll
        for (int kk = 0; kk < 8; kk++) {
            uint32_t aP0[4], aP1[4];
            ldsm4(aP0[0], aP0[1], aP0[2], aP0[3], pAdrM[0] + kk * 32);
            ldsm4(aP1[0], aP1[1], aP1[2], aP1[3], pAdrM[1] + kk * 32);
            uint32_t bv[16];
            const uint32_t vAdr = vsAdr + vRow + vCol + (uint32_t)(kk * 32);
            #pragma unroll
            for (int j = 0; j < 4; j++)
                ldsm4(bv[4*j], bv[4*j+1], bv[4*j+2], bv[4*j+3],
                      vAdr + (uint32_t)(j * 16 * APAD * 4));
            #pragma unroll
            for (int nb = 0; nb < 8; nb++) {
                const uint32_t* bp = &bv[4 * (nb >> 1) + 2 * (nb & 1)];
                mma_tf32(Oa[0][nb], aP0, bp);
                mma_tf32(Oa[1][nb], aP1, bp);
            }
        }
        __syncwarp();
    }

    // Finalize
    #pragma unroll
    for (int mi = 0; mi < 2; mi++) {
        float l0 = ls[mi][0], l1 = ls[mi][1];
        l0 += __shfl_xor_sync(0xffffffffu, l0, 1);
        l0 += __shfl_xor_sync(0xffffffffu, l0, 2);
        l1 += __shfl_xor_sync(0xffffffffu, l1, 1);
        l1 += __shfl_xor_sync(0xffffffffu, l1, 2);
        float inv0 = 1.f / l0, inv1 = 1.f / l1;

        float* Ob = g_O + ((size_t)(b * SEQ + q0 + w * 32 + mi * 16)) * DMODEL + h * DH;
        #pragma unroll
        for (int nb = 0; nb < 8; nb++) {
            *(float2*)(Ob + (size_t)gid * DMODEL + nb * 8 + 2 * tid4) =
                make_float2(to_tf32_rn(Oa[mi][nb][0] * inv0), to_tf32_rn(Oa[mi][nb][1] * inv0));
            *(float2*)(Ob + (size_t)(gid + 8) * DMODEL + nb * 8 + 2 * tid4) =
                make_float2(to_tf32_rn(Oa[mi][nb][2] * inv1), to_tf32_rn(Oa[mi][nb][3] * inv1));
        }
    }
}

// ---------------------------------------------------------------------------
// Launch:  inputs 0=queries 1=keys 2=values 3=masks 4=Wq 5=Wk 6=Wv 7=Wo
// ---------------------------------------------------------------------------
extern "C" void kernel_launch(void* const* d_in, const int* in_sizes, int n_in,
                              void* d_out, int out_size) {
    const int* masks = (const int*)d_in[3];
    float* out = (float*)d_out;

    float *gq, *gkc, *go, *gwt, *gr;
    cudaGetSymbolAddress((void**)&gq,  g_Q);
    cudaGetSymbolAddress((void**)&gkc, g_Kc);
    cudaGetSymbolAddress((void**)&go,  g_O);
    cudaGetSymbolAddress((void**)&gwt, g_Wt);
    cudaGetSymbolAddress((void**)&gr,  g_R);

    cudaFuncSetAttribute(gemm_tf32_kernel<true>,
                         cudaFuncAttributeMaxDynamicSharedMemorySize, SM_GEMM_BYTES);
    cudaFuncSetAttribute(gemm_tf32_kernel<false>,
                         cudaFuncAttributeMaxDynamicSharedMemorySize, SM_GEMM_BYTES);
    cudaFuncSetAttribute(attn_mma_kernel,
                         cudaFuncAttributeMaxDynamicSharedMemorySize, ATT_SMEM);

    // 1. Tiny compaction index pass
    compact_idx_kernel<<<BATCH, 32>>>(masks);

    // 2. Fused prep: roundq + weight transpose + key/value input compaction
    PrepArgs pp;
    pp.q = (const float4*)d_in[0];
    for (int i = 0; i < 4; i++) pp.ws[i] = (const float*)d_in[4 + i];
    pp.kv[0] = (const float*)d_in[1];
    pp.kv[1] = (const float*)d_in[2];
    prep_kernel<<<dim3(MTOT, 1, 4), 256>>>(pp);

    const size_t NN  = (size_t)MTOT * DMODEL;
    const size_t NN2 = (size_t)DMODEL * DMODEL;

    // 3. Fused Q/K/V projections; z>=1 operate on compacted rows (early-exit rest)
    GemmBatch g1;
    g1.A[0] = gr + 0 * NN; g1.B[0] = gwt + 0 * NN2; g1.C[0] = gq;
    g1.A[1] = gr + 1 * NN; g1.B[1] = gwt + 1 * NN2; g1.C[1] = gkc;
    g1.A[2] = gr + 2 * NN; g1.B[2] = gwt + 2 * NN2; g1.C[2] = nullptr;  // vt store
    gemm_tf32_kernel<true><<<dim3(DMODEL / BN, MTOT / BM, 3), 256, SM_GEMM_BYTES>>>(g1);

    // 4. Attention over compacted KV
    dim3 ga(SEQ / ATT_BQ, NH, BATCH);  // (16, 16, 2) = 512 CTAs, 128 threads
    attn_mma_kernel<<<ga, 128, ATT_SMEM>>>();

    // 5. Output projection
    GemmBatch g2;
    g2.A[0] = go; g2.B[0] = gwt + 3 * NN2; g2.C[0] = out;
    g2.A[1] = g2.A[2] = nullptr; g2.B[1] = g2.B[2] = nullptr; g2.C[1] = g2.C[2] = nullptr;
    gemm_tf32_kernel<false><<<dim3(DMODEL / BN, MTOT / BM, 1), 256, SM_GEMM_BYTES>>>(g2);
}